// round 1
// baseline (speedup 1.0000x reference)
#include <cuda_runtime.h>
#include <cstdint>

// ---------------------------------------------------------------------------
// TensorizedEmbedding: out[b, :] for token idx is the TT contraction
//   digits: d0 = idx/4000, d1 = (idx/400)%10, d2 = (idx/20)%20, d3 = idx%20
//   out[((a*4+m)*6+m2)*8+q] = sum_{r0,r',r} core0[0,d0,a,r0] core1[r0,d1,m,r']
//                                            core2[r',d2,m2,r] core3[r,d3,q,0]
// Precompute:
//   g_res1[c01=d0*10+d1][am=a*4+m][r']  (80 x 16 x 16)
//   g_H   [c23=d2*20+d3][r'][m2*8+q]    (400 x 16 x 48)
// Per token:  out_row[16 x 48] = res1[c01] (16x16) @ H[c23] (16x48)
// ---------------------------------------------------------------------------

__device__ __align__(16) float g_res1[80 * 256];     // 80 KB
__device__ __align__(16) float g_H[400 * 768];       // 1.23 MB

// ---------------- precompute: res1 (blocks 0..79) and H (blocks 80..479) ----
__global__ __launch_bounds__(256) void precompute_kernel(
    const float* __restrict__ c0, const float* __restrict__ c1,
    const float* __restrict__ c2, const float* __restrict__ c3)
{
    int b = blockIdx.x;
    if (b < 80) {
        // res1[c01][am][r'] = sum_r0 core0[0,d0,a,r0] * core1[r0,d1,m,r']
        // core0: [1,8,4,16]  -> c0[d0*64 + a*16 + r0]
        // core1: [16,10,4,16]-> c1[r0*640 + d1*64 + m*16 + r']
        int d0 = b / 10, d1 = b % 10;
        int t  = threadIdx.x;         // 256 entries, one per thread
        int am = t >> 4, rp = t & 15;
        int a  = am >> 2, m = am & 3;
        float acc = 0.f;
        #pragma unroll
        for (int r0 = 0; r0 < 16; r0++)
            acc += c0[d0 * 64 + a * 16 + r0] * c1[r0 * 640 + d1 * 64 + m * 16 + rp];
        g_res1[b * 256 + t] = acc;
    } else {
        // H[c23][rp][m2*8+q] = sum_r core2[rp,d2,m2,r] * core3[r,d3,q,0]
        // core2: [16,20,6,16] -> c2[rp*1920 + d2*96 + m2*16 + r]
        // core3: [16,20,8,1]  -> c3[r*160 + d3*8 + q]
        int c23 = b - 80;
        int d2 = c23 / 20, d3 = c23 % 20;
        for (int e = threadIdx.x; e < 768; e += 256) {
            int rp = e / 48, mq = e % 48;
            int m2 = mq >> 3, q = mq & 7;
            float acc = 0.f;
            #pragma unroll
            for (int r = 0; r < 16; r++)
                acc += c2[rp * 1920 + d2 * 96 + m2 * 16 + r] * c3[r * 160 + d3 * 8 + q];
            g_H[c23 * 768 + e] = acc;
        }
    }
}

// ---------------- main: one thread = (token, am, m2) -> 8 outputs -----------
// block = 384 threads = 4 tokens x 96 threads; 96 = 3 full warps per token.
__global__ __launch_bounds__(384) void embed_kernel(
    const int* __restrict__ x, float* __restrict__ out, int B)
{
    int tid = threadIdx.x;
    int tok = blockIdx.x * 4 + tid / 96;
    if (tok >= B) return;
    int p  = tid % 96;
    int am = p / 6;
    int m2 = p - am * 6;

    int idx = x[tok];
    int c01 = idx / 400;          // d0*10 + d1
    int c23 = idx - c01 * 400;    // d2*20 + d3

    // load res1 row (16 floats)
    const float4* r1p = reinterpret_cast<const float4*>(g_res1 + c01 * 256 + am * 16);
    float4 v0 = r1p[0], v1 = r1p[1], v2 = r1p[2], v3 = r1p[3];
    float rv[16] = { v0.x, v0.y, v0.z, v0.w,  v1.x, v1.y, v1.z, v1.w,
                     v2.x, v2.y, v2.z, v2.w,  v3.x, v3.y, v3.z, v3.w };

    const float* hp = g_H + c23 * 768 + m2 * 8;

    unsigned long long acc0 = 0ull, acc1 = 0ull, acc2 = 0ull, acc3 = 0ull; // f32x2 pairs (0,0)

    #pragma unroll
    for (int r = 0; r < 16; r++) {
        unsigned int wu = __float_as_uint(rv[r]);
        unsigned long long w2;
        asm("mov.b64 %0, {%1, %1};" : "=l"(w2) : "r"(wu));
        const ulonglong2* h2 = reinterpret_cast<const ulonglong2*>(hp + r * 48);
        ulonglong2 hA = h2[0];
        ulonglong2 hB = h2[1];
        asm("fma.rn.f32x2 %0, %1, %2, %0;" : "+l"(acc0) : "l"(w2), "l"(hA.x));
        asm("fma.rn.f32x2 %0, %1, %2, %0;" : "+l"(acc1) : "l"(w2), "l"(hA.y));
        asm("fma.rn.f32x2 %0, %1, %2, %0;" : "+l"(acc2) : "l"(w2), "l"(hB.x));
        asm("fma.rn.f32x2 %0, %1, %2, %0;" : "+l"(acc3) : "l"(w2), "l"(hB.y));
    }

    float o0, o1, o2, o3, o4, o5, o6, o7;
    asm("mov.b64 {%0, %1}, %2;" : "=f"(o0), "=f"(o1) : "l"(acc0));
    asm("mov.b64 {%0, %1}, %2;" : "=f"(o2), "=f"(o3) : "l"(acc1));
    asm("mov.b64 {%0, %1}, %2;" : "=f"(o4), "=f"(o5) : "l"(acc2));
    asm("mov.b64 {%0, %1}, %2;" : "=f"(o6), "=f"(o7) : "l"(acc3));

    float* op = out + (size_t)tok * 768 + am * 48 + m2 * 8;
    reinterpret_cast<float4*>(op)[0] = make_float4(o0, o1, o2, o3);
    reinterpret_cast<float4*>(op)[1] = make_float4(o4, o5, o6, o7);
}

extern "C" void kernel_launch(void* const* d_in, const int* in_sizes, int n_in,
                              void* d_out, int out_size)
{
    const int*   x  = (const int*)d_in[0];
    const float* c0 = (const float*)d_in[1];
    const float* c1 = (const float*)d_in[2];
    const float* c2 = (const float*)d_in[3];
    const float* c3 = (const float*)d_in[4];
    float* out = (float*)d_out;

    int B = in_sizes[0];  // 32768 tokens

    precompute_kernel<<<480, 256>>>(c0, c1, c2, c3);
    embed_kernel<<<(B + 3) / 4, 384>>>(x, out, B);
}

// round 4
// speedup vs baseline: 2.3535x; 2.3535x over previous
#include <cuda_runtime.h>
#include <cstdint>

// ---------------------------------------------------------------------------
// TensorizedEmbedding via two precomputed tables:
//   g_res1T[c01=d0*10+d1][r'][am]      (80 x 16 x 16)  -- TRANSPOSED (r' major)
//   g_H    [c23=d2*20+d3][r'][m2*8+q]  (400 x 16 x 48)
// Per token: out_row[16 x 48] = res1[c01]^ (16x16, stored r-major) @ H[c23]
// Main kernel: 1 thread = 4am x 8col tile (32 outputs), 24 threads/token.
// ---------------------------------------------------------------------------

__device__ __align__(16) float g_res1T[80 * 256];    // 80 KB
__device__ __align__(16) float g_H[400 * 768];       // 1.23 MB

// ---------------- precompute: res1T (blocks 0..79) and H (blocks 80..479) ---
__global__ __launch_bounds__(256) void precompute_kernel(
    const float* __restrict__ c0, const float* __restrict__ c1,
    const float* __restrict__ c2, const float* __restrict__ c3)
{
    int b = blockIdx.x;
    if (b < 80) {
        // res1T[c01][rp][am] = sum_r0 core0[0,d0,a,r0] * core1[r0,d1,m,rp]
        // core0: [1,8,4,16]   -> c0[d0*64 + a*16 + r0]
        // core1: [16,10,4,16] -> c1[r0*640 + d1*64 + m*16 + rp]
        int d0 = b / 10, d1 = b % 10;
        int t  = threadIdx.x;         // 256 entries
        int rp = t >> 4, am = t & 15; // store r-major: [rp][am]
        int a  = am >> 2, m = am & 3;
        float acc = 0.f;
        #pragma unroll
        for (int r0 = 0; r0 < 16; r0++)
            acc += c0[d0 * 64 + a * 16 + r0] * c1[r0 * 640 + d1 * 64 + m * 16 + rp];
        g_res1T[b * 256 + rp * 16 + am] = acc;
    } else {
        // H[c23][rp][m2*8+q] = sum_r core2[rp,d2,m2,r] * core3[r,d3,q,0]
        // core2: [16,20,6,16] -> c2[rp*1920 + d2*96 + m2*16 + r]
        // core3: [16,20,8,1]  -> c3[r*160 + d3*8 + q]
        int c23 = b - 80;
        int d2 = c23 / 20, d3 = c23 % 20;
        for (int e = threadIdx.x; e < 768; e += 256) {
            int rp = e / 48, mq = e % 48;
            int m2 = mq >> 3, q = mq & 7;
            float acc = 0.f;
            #pragma unroll
            for (int r = 0; r < 16; r++)
                acc += c2[rp * 1920 + d2 * 96 + m2 * 16 + r] * c3[r * 160 + d3 * 8 + q];
            g_H[c23 * 768 + e] = acc;
        }
    }
}

// ---------------- main kernel ----------------------------------------------
// thread t (global): tok = t/24, sub = t%24
//   amg = sub & 3  -> rows am = amg*4 .. amg*4+3
//   cg  = sub >> 2 -> cols  c = cg*8 .. cg*8+7
// Per k-step: 1x LDG.128 res1T (4 am scalars) + 2x LDG.128 H (8 cols)
//             -> 16 packed f32x2 FMAs into 16 accumulators.
__global__ __launch_bounds__(192, 4) void embed_kernel(
    const int* __restrict__ x, float* __restrict__ out, int B)
{
    int t   = blockIdx.x * 192 + threadIdx.x;
    int tok = t / 24;
    if (tok >= B) return;
    int sub = t - tok * 24;
    int amg = sub & 3;
    int cg  = sub >> 2;

    int idx = __ldg(x + tok);
    int c01 = idx / 400;          // d0*10 + d1
    int c23 = idx - c01 * 400;    // d2*20 + d3

    const float4*     rp = reinterpret_cast<const float4*>(g_res1T + c01 * 256 + amg * 4);
    const ulonglong2* hp = reinterpret_cast<const ulonglong2*>(g_H + c23 * 768 + cg * 8);

    // acc[i][j]: am row i (0..3), col pair j (0..3) -> packed 2 floats
    unsigned long long acc[4][4];
    #pragma unroll
    for (int i = 0; i < 4; i++)
        #pragma unroll
        for (int j = 0; j < 4; j++) acc[i][j] = 0ull;

    #pragma unroll
    for (int r = 0; r < 16; r++) {
        float4 w = rp[r * 4];                 // res1T row r: 4 am scalars (16-float row)
        // H row r: stride 48 floats = 12 ulonglong2 elements
        ulonglong2 hA = hp[r * 12];           // cols 0..3 (2 pairs)
        ulonglong2 hB = hp[r * 12 + 1];       // cols 4..7 (2 pairs)

        unsigned long long w2[4];
        {
            unsigned int u0 = __float_as_uint(w.x), u1 = __float_as_uint(w.y);
            unsigned int u2 = __float_as_uint(w.z), u3 = __float_as_uint(w.w);
            asm("mov.b64 %0, {%1, %1};" : "=l"(w2[0]) : "r"(u0));
            asm("mov.b64 %0, {%1, %1};" : "=l"(w2[1]) : "r"(u1));
            asm("mov.b64 %0, {%1, %1};" : "=l"(w2[2]) : "r"(u2));
            asm("mov.b64 %0, {%1, %1};" : "=l"(w2[3]) : "r"(u3));
        }

        #pragma unroll
        for (int i = 0; i < 4; i++) {
            asm("fma.rn.f32x2 %0, %1, %2, %0;" : "+l"(acc[i][0]) : "l"(w2[i]), "l"(hA.x));
            asm("fma.rn.f32x2 %0, %1, %2, %0;" : "+l"(acc[i][1]) : "l"(w2[i]), "l"(hA.y));
            asm("fma.rn.f32x2 %0, %1, %2, %0;" : "+l"(acc[i][2]) : "l"(w2[i]), "l"(hB.x));
            asm("fma.rn.f32x2 %0, %1, %2, %0;" : "+l"(acc[i][3]) : "l"(w2[i]), "l"(hB.y));
        }
    }

    // store: 4 rows (stride 48 floats), 8 floats each, 16B-aligned
    float* op = out + (size_t)tok * 768 + amg * (4 * 48) + cg * 8;
    #pragma unroll
    for (int i = 0; i < 4; i++) {
        ulonglong2* o2 = reinterpret_cast<ulonglong2*>(op + i * 48);
        o2[0] = make_ulonglong2(acc[i][0], acc[i][1]);
        o2[1] = make_ulonglong2(acc[i][2], acc[i][3]);
    }
}

extern "C" void kernel_launch(void* const* d_in, const int* in_sizes, int n_in,
                              void* d_out, int out_size)
{
    const int*   x  = (const int*)d_in[0];
    const float* c0 = (const float*)d_in[1];
    const float* c1 = (const float*)d_in[2];
    const float* c2 = (const float*)d_in[3];
    const float* c3 = (const float*)d_in[4];
    float* out = (float*)d_out;

    int B = in_sizes[0];  // 32768 tokens

    precompute_kernel<<<480, 256>>>(c0, c1, c2, c3);
    // 24 threads per token, 192 threads per block -> 8 tokens per block
    embed_kernel<<<(B + 7) / 8, 192>>>(x, out, B);
}